// round 8
// baseline (speedup 1.0000x reference)
#include <cuda_runtime.h>
#include <cstdint>
#include <cstddef>

// Problem dims
#define T_STEPS 512
#define BATCH   256
#define DIN     128
#define HDIM    256
#define PDIM    128
#define DH      384            // DIN + HDIM

// 32 clusters x 4 CTAs. Each cluster owns 8 batch rows for all T.
// Rank r owns prototypes [r*32, r*32+32) and hidden cols [r*64, r*64+64) of all gates.
#define CLUSTER 4
#define BT      8
#define NTHR    512

// Shared-memory layout (offsets in floats)
#define OFF_PROTO 0                 // [32][384]  rank's prototype slice
#define OFF_WT    12288             // [128][256] WT[i][g*64+hl], row i <-> p=(rank*32+i)&127
#define OFF_C     45056             // [8][384]   combined [x | h]
#define OFF_KT    48128             // [128][8]   kT[i][b], row i <-> p=(rank*32+i)&127
#define OFF_PRE   49152             // [8][256]   gate preactivations (rank's cols)
#define OFF_BIAS  51200             // [256]
#define OFF_PN    51456             // [32]       ||proto_p||^2
#define OFF_CNX   51488             // [8]        x-part of ||c_b||^2
#define OFF_CNH   51496             // [8]        h-part of ||c_b||^2
#define OFF_KBAR  51504             // u64 mbarrier (k exchange)
#define OFF_HBAR  51506             // u64 mbarrier (h exchange)
#define SMEM_FLOATS 51508
#define SMEM_BYTES  (SMEM_FLOATS * 4)   // 206032 B

typedef unsigned long long ull;

// ---------------- helpers ----------------

__device__ __forceinline__ uint32_t cvta_shared_u32(const void* p) {
    uint32_t a;
    asm("{ .reg .u64 t; cvta.to.shared.u64 t, %1; cvt.u32.u64 %0, t; }"
        : "=r"(a) : "l"(p));
    return a;
}

__device__ __forceinline__ void stc_f32(uint32_t saddr, uint32_t rankv, float v) {
    uint32_t ra;
    asm volatile("mapa.shared::cluster.u32 %0, %1, %2;" : "=r"(ra) : "r"(saddr), "r"(rankv));
    asm volatile("st.shared::cluster.f32 [%0], %1;" :: "r"(ra), "f"(v) : "memory");
}

// arrive (release, cluster scope) on CTA `rankv`'s mbarrier at local offset saddr
__device__ __forceinline__ void mbar_arrive_remote(uint32_t saddr, uint32_t rankv) {
    uint32_t ra;
    asm volatile("mapa.shared::cluster.u32 %0, %1, %2;" : "=r"(ra) : "r"(saddr), "r"(rankv));
    asm volatile("mbarrier.arrive.release.cluster.shared::cluster.b64 _, [%0];"
                 :: "r"(ra) : "memory");
}

// wait on local mbarrier with acquire-cluster semantics
__device__ __forceinline__ void mbar_wait(uint32_t saddr, uint32_t phase) {
    uint32_t done;
    do {
        asm volatile(
            "{\n\t.reg .pred p;\n\t"
            "mbarrier.try_wait.parity.acquire.cluster.shared::cta.b64 p, [%1], %2, 0x989680;\n\t"
            "selp.b32 %0, 1, 0, p;\n\t}"
            : "=r"(done) : "r"(saddr), "r"(phase) : "memory");
    } while (!done);
}

__device__ __forceinline__ ull pack2(float lo, float hi) {
    ull r; asm("mov.b64 %0, {%1, %2};" : "=l"(r) : "f"(lo), "f"(hi)); return r;
}
__device__ __forceinline__ ull ffma2(ull a, ull b, ull c) {
    ull d; asm("fma.rn.f32x2 %0, %1, %2, %3;" : "=l"(d) : "l"(a), "l"(b), "l"(c)); return d;
}
__device__ __forceinline__ void unpack2(ull v, float& lo, float& hi) {
    asm("mov.b64 {%0, %1}, %2;" : "=f"(lo), "=f"(hi) : "l"(v));
}

__device__ __forceinline__ float sigf(float x) {
    return __fdividef(1.f, 1.f + __expf(-x));
}
__device__ __forceinline__ float tanhf_fast(float x) {
    float ax = fabsf(x);
    float e  = __expf(-2.f * ax);
    float r  = __fdividef(1.f - e, 1.f + e);
    return copysignf(r, x);
}

// ---------------- kernel ----------------

__global__ void __cluster_dims__(CLUSTER, 1, 1) __launch_bounds__(NTHR, 1)
qlstm_kernel(const float* __restrict__ xin,   const float* __restrict__ proto,
             const float* __restrict__ Wf_p,  const float* __restrict__ bf_p,
             const float* __restrict__ Wi_p,  const float* __restrict__ bi_p,
             const float* __restrict__ Wg_p,  const float* __restrict__ bg_p,
             const float* __restrict__ Wo_p,  const float* __restrict__ bo_p,
             float* __restrict__ out)
{
    extern __shared__ float sm[];
    float* protoS = sm + OFF_PROTO;
    float* WTs    = sm + OFF_WT;
    float* cS     = sm + OFF_C;
    float* kTs    = sm + OFF_KT;
    float* preS   = sm + OFF_PRE;
    float* biasS  = sm + OFF_BIAS;
    float* pnS    = sm + OFF_PN;
    float* cnxS   = sm + OFF_CNX;
    float* cnhS   = sm + OFF_CNH;

    const int tid  = threadIdx.x;
    const int lane = tid & 31;
    const int w    = tid >> 5;                  // warp id 0..15
    const int rank = (int)(blockIdx.x & 3);
    const int B0   = (int)(blockIdx.x >> 2) * BT;
    const uint32_t smem_u32 = cvta_shared_u32(sm);
    const uint32_t kbar = smem_u32 + OFF_KBAR * 4u;
    const uint32_t hbar = smem_u32 + OFF_HBAR * 4u;

    // ---------- one-time init ----------
    {
        const float* psrc = proto + (size_t)(rank * 32) * DH;
        for (int i = tid; i < 32 * DH; i += NTHR) protoS[i] = psrc[i];
    }
    {
        // WT row i holds W columns for p = (rank*32 + i) & 127  (rotated layout)
        #pragma unroll
        for (int g = 0; g < 4; g++) {
            const float* Wg_ = (g == 0) ? Wf_p : (g == 1) ? Wi_p : (g == 2) ? Wg_p : Wo_p;
            for (int idx = tid; idx < PDIM * 64; idx += NTHR) {
                int hl = idx >> 7;          // 0..63
                int i  = idx & 127;         // rotated row
                int p  = (rank * 32 + i) & 127;
                WTs[i * 256 + g * 64 + hl] = Wg_[(size_t)(rank * 64 + hl) * PDIM + p];
            }
        }
    }
    if (tid < 64) {
        biasS[        tid] = bf_p[rank * 64 + tid];
        biasS[ 64 +   tid] = bi_p[rank * 64 + tid];
        biasS[128 +   tid] = bg_p[rank * 64 + tid];
        biasS[192 +   tid] = bo_p[rank * 64 + tid];
    }
    for (int i = tid; i < BT * DH; i += NTHR) cS[i] = 0.f;
    if (tid == 0) {
        asm volatile("mbarrier.init.shared.b64 [%0], %1;" :: "r"(kbar), "r"(4u) : "memory");
        asm volatile("mbarrier.init.shared.b64 [%0], %1;" :: "r"(hbar), "r"(4u) : "memory");
    }
    __syncthreads();

    if (tid < 32) {
        const float4* pr = (const float4*)(protoS + tid * DH);
        float s = 0.f;
        #pragma unroll 8
        for (int q = 0; q < DH / 4; q++) {
            float4 v = pr[q];
            s += v.x * v.x + v.y * v.y + v.z * v.z + v.w * v.w;
        }
        pnS[tid] = s;
    }
    __syncthreads();
    // full HW cluster barrier once: mbarrier inits visible before any arrivals
    asm volatile("barrier.cluster.arrive.aligned;" ::: "memory");
    asm volatile("barrier.cluster.wait.aligned;"   ::: "memory");

    // pre-arm hbar so the t=0 wait passes (h(−1)=0 already in cS)
    if (tid < 4) mbar_arrive_remote(hbar, (uint32_t)tid);
    uint32_t phik = 0, phih = 0;

    float cxr = 0.f;   // cell state for this thread's (b = tid>>6, hl = tid&63)

    // prefetch x for t=0: 8*128 floats = 512 float2
    float2 xreg = ((const float2*)(xin + (size_t)B0 * DIN))[tid];

    for (int t = 0; t < T_STEPS; t++) {
        // ---------- phase A: x into combined buffer, wait h, split norms ----------
        ((float2*)(cS + (tid >> 6) * DH))[tid & 63] = xreg;
        if (t + 1 < T_STEPS) {
            xreg = ((const float2*)(xin + (size_t)(t + 1) * BATCH * DIN
                                        + (size_t)B0 * DIN))[tid];
        }
        mbar_wait(hbar, phih);      // h(t-1) from all ranks visible
        phih ^= 1;
        __syncthreads();            // x part visible CTA-wide
        if (w < 8) {
            // x-norm for b = w
            const float4* cb = (const float4*)(cS + w * DH);
            float4 a0 = cb[lane];
            float s = a0.x * a0.x + a0.y * a0.y + a0.z * a0.z + a0.w * a0.w;
            #pragma unroll
            for (int m = 16; m >= 1; m >>= 1)
                s += __shfl_xor_sync(0xffffffffu, s, m);
            if (lane == 0) cnxS[w] = s;
        } else {
            // h-norm for b = w - 8
            const float4* cb = (const float4*)(cS + (w - 8) * DH);
            float4 a1 = cb[32 + lane];
            float4 a2 = cb[64 + lane];
            float s = a1.x * a1.x + a1.y * a1.y + a1.z * a1.z + a1.w * a1.w
                    + a2.x * a2.x + a2.y * a2.y + a2.z * a2.z + a2.w * a2.w;
            #pragma unroll
            for (int m = 16; m >= 1; m >>= 1)
                s += __shfl_xor_sync(0xffffffffu, s, m);
            if (lane == 0) cnhS[w - 8] = s;
        }
        __syncthreads();

        // ---------- phase B: RBF kernel, 16 warps x (2 protos x 8 b) ----------
        {
            const int pp0 = w * 2;          // warp owns local protos pp0, pp0+1
            ull acc2[16];
            #pragma unroll
            for (int i = 0; i < 16; i++) acc2[i] = 0ull;

            #pragma unroll 3
            for (int jc = 0; jc < 6; jc++) {
                const int jj = jc * 32 + lane;       // f2 index 0..191
                ull cv2[8], pv2[2];
                #pragma unroll
                for (int b2 = 0; b2 < 8; b2++)
                    cv2[b2] = ((const ull*)(cS + b2 * DH))[jj];
                #pragma unroll
                for (int q = 0; q < 2; q++)
                    pv2[q] = ((const ull*)(protoS + (pp0 + q) * DH))[jj];
                #pragma unroll
                for (int b2 = 0; b2 < 8; b2++) {
                    #pragma unroll
                    for (int q = 0; q < 2; q++)
                        acc2[b2 * 2 + q] = ffma2(cv2[b2], pv2[q], acc2[b2 * 2 + q]);
                }
            }
            // collapse packed halves, then 4-round xor-merge over 16 items
            float acc[16];
            #pragma unroll
            for (int i = 0; i < 16; i++) {
                float lo, hi;
                unpack2(acc2[i], lo, hi);
                acc[i] = lo + hi;
            }
            #pragma unroll
            for (int s5 = 0; s5 < 4; s5++) {
                const int m = 1 << s5;
                const int L = 16 >> s5;
                const bool hi = (lane & m) != 0;
                #pragma unroll
                for (int i = 0; i < (L >> 1); i++) {
                    float mine = hi ? acc[2 * i + 1] : acc[2 * i];
                    float send = hi ? acc[2 * i]     : acc[2 * i + 1];
                    acc[i] = mine + __shfl_xor_sync(0xffffffffu, send, m);
                }
            }
            // combine the two half-warps (lanes l and l^16 hold same index)
            acc[0] += __shfl_xor_sync(0xffffffffu, acc[0], 16);

            if (lane < 16) {
                const int q  = lane & 1;
                const int b  = (lane >> 1) & 7;
                const int lp = pp0 + q;              // local proto 0..31
                const float d2 = cnxS[b] + cnhS[b] + pnS[lp] - 2.f * acc[0];
                const float kv = __expf(-d2);        // GAMMA = 1
                // own slot (rotated layout: own protos land at rows [0,32))
                kTs[lp * 8 + b] = kv;
                // peers: rank's protos land at row ((rank-rho)&3)*32 + lp
                #pragma unroll
                for (int d = 1; d < 4; d++) {
                    const int rho  = (rank + d) & 3;
                    const int slot = (4 - d) * 32 + lp;
                    stc_f32(smem_u32 + (uint32_t)(OFF_KT + slot * 8 + b) * 4u,
                            (uint32_t)rho, kv);
                }
            }
        }
        __syncthreads();                       // own-kT STS + all stc issued
        if (tid < 4) mbar_arrive_remote(kbar, (uint32_t)tid);

        // ---------- phase C: thread = (column hc, b-half) — full dots ----------
        const int hc   = tid & 255;            // rank-local gate column
        const int half = tid >> 8;             // 0: b0..3, 1: b4..7
        ull a0, a1;
        {
            const float bv = biasS[hc];
            a0 = pack2(bv, bv); a1 = a0;
        }
        const float* wcol  = WTs + hc;
        const float* kbase = kTs + half * 4;

        // part 1: own 32 rows (overlaps k-exchange)
        #pragma unroll 4
        for (int i = 0; i < 32; i++) {
            const ulonglong2 kx = *(const ulonglong2*)(kbase + i * 8);
            const float wv = wcol[i * 256];
            const ull wv2 = pack2(wv, wv);
            a0 = ffma2(kx.x, wv2, a0);
            a1 = ffma2(kx.y, wv2, a1);
        }
        mbar_wait(kbar, phik);                 // peer kT rows now visible
        phik ^= 1;

        // part 2: remaining 96 rows
        #pragma unroll 4
        for (int i = 32; i < 128; i++) {
            const ulonglong2 kx = *(const ulonglong2*)(kbase + i * 8);
            const float wv = wcol[i * 256];
            const ull wv2 = pack2(wv, wv);
            a0 = ffma2(kx.x, wv2, a0);
            a1 = ffma2(kx.y, wv2, a1);
        }
        {
            float lo, hi;
            unpack2(a0, lo, hi);
            preS[(half * 4 + 0) * 256 + hc] = lo;
            preS[(half * 4 + 1) * 256 + hc] = hi;
            unpack2(a1, lo, hi);
            preS[(half * 4 + 2) * 256 + hc] = lo;
            preS[(half * 4 + 3) * 256 + hc] = hi;
        }
        __syncthreads();

        // ---------- gates: 512 threads x 1 (b,hl), cx in register ----------
        const bool deliver = (t + 1 < T_STEPS);
        float hval;
        {
            const int b  = tid >> 6;
            const int hl = tid & 63;
            const float pf  = preS[b * 256 +       hl];
            const float pi_ = preS[b * 256 +  64 + hl];
            const float pg_ = preS[b * 256 + 128 + hl];
            const float po  = preS[b * 256 + 192 + hl];
            const float f  = sigf(pf);
            const float ii = sigf(pi_);
            const float g  = tanhf_fast(pg_);
            const float oo = sigf(po);
            cxr = f * cxr + ii * g;
            hval = oo * tanhf_fast(cxr);

            if (deliver) {
                // own combined buffer + 3 peers
                cS[b * DH + DIN + rank * 64 + hl] = hval;
                const uint32_t a = smem_u32
                    + (uint32_t)(OFF_C + b * DH + DIN + rank * 64 + hl) * 4u;
                #pragma unroll
                for (int d = 1; d < 4; d++)
                    stc_f32(a, (uint32_t)((rank + d) & 3), hval);
            }
        }
        if (deliver) {
            __syncthreads();
            if (tid < 4) mbar_arrive_remote(hbar, (uint32_t)tid);
        }

        // global stores overlap the h-exchange propagation
        {
            const int b  = tid >> 6;
            const int hl = tid & 63;
            const size_t obase = (size_t)t * BATCH * HDIM
                               + (size_t)(B0 + b) * HDIM + rank * 64 + hl;
            out[obase] = hval;
            if (t == T_STEPS - 1) {
                const size_t fbase = (size_t)T_STEPS * BATCH * HDIM
                                   + (size_t)(B0 + b) * HDIM + rank * 64 + hl;
                out[fbase] = hval;                               // hx
                out[fbase + (size_t)BATCH * HDIM] = cxr;         // cx
            }
        }
    }

    // terminal cluster barrier: no CTA may exit while peers might still have
    // st.shared::cluster / remote mbarrier traffic targeting its SMEM
    asm volatile("barrier.cluster.arrive.aligned;" ::: "memory");
    asm volatile("barrier.cluster.wait.aligned;"   ::: "memory");
}

extern "C" void kernel_launch(void* const* d_in, const int* in_sizes, int n_in,
                              void* d_out, int out_size) {
    (void)in_sizes; (void)n_in; (void)out_size;
    const float* xin   = (const float*)d_in[0];
    const float* proto = (const float*)d_in[1];
    const float* Wf    = (const float*)d_in[2];
    const float* bf    = (const float*)d_in[3];
    const float* Wi    = (const float*)d_in[4];
    const float* bi    = (const float*)d_in[5];
    const float* Wg    = (const float*)d_in[6];
    const float* bg    = (const float*)d_in[7];
    const float* Wo    = (const float*)d_in[8];
    const float* bo    = (const float*)d_in[9];
    float* out = (float*)d_out;

    cudaFuncSetAttribute(qlstm_kernel,
                         cudaFuncAttributeMaxDynamicSharedMemorySize, SMEM_BYTES);
    qlstm_kernel<<<(BATCH / BT) * CLUSTER, NTHR, SMEM_BYTES>>>(
        xin, proto, Wf, bf, Wi, bi, Wg, bg, Wo, bo, out);
}